// round 10
// baseline (speedup 1.0000x reference)
#include <cuda_runtime.h>
#include <cuda_fp16.h>
#include <cstdint>

// Problem constants: B=4, S=256, D_MODEL=2048, H=256, HEAD_DIM=8
#define TOKENS   1024
#define DM       2048
#define NHEADS   256

// ---------------------------------------------------------------------------
// Scratch (__device__ globals; allocation-free rule)
// ---------------------------------------------------------------------------
__device__ __align__(16) float  g_q[TOKENS * DM];
__device__ __align__(16) float  g_k[TOKENS * DM];
__device__ __align__(16) float  g_v[TOKENS * DM];
__device__ __align__(16) __half g_ah[TOKENS * DM];      // attn out (fp16)
__device__ __align__(16) __half g_xh[TOKENS * DM];      // x (fp16)
__device__ __align__(16) __half g_wth[4 * DM * DM];     // W^T fp16 (Wq,Wk,Wv,Wo), [N][K]

__device__ __forceinline__ void cp16(uint32_t saddr, const void* gptr) {
    asm volatile("cp.async.cg.shared.global [%0], [%1], 16;\n" :: "r"(saddr), "l"(gptr));
}
__device__ __forceinline__ void mma_f16(float* c, const uint32_t* a, const uint32_t* b) {
    asm volatile(
        "mma.sync.aligned.m16n8k16.row.col.f32.f16.f16.f32 "
        "{%0,%1,%2,%3}, {%4,%5,%6,%7}, {%8,%9}, {%0,%1,%2,%3};"
        : "+f"(c[0]), "+f"(c[1]), "+f"(c[2]), "+f"(c[3])
        : "r"(a[0]), "r"(a[1]), "r"(a[2]), "r"(a[3]), "r"(b[0]), "r"(b[1]));
}
__device__ __forceinline__ void ldsm4(uint32_t& r0, uint32_t& r1, uint32_t& r2, uint32_t& r3,
                                      uint32_t addr) {
    asm volatile("ldmatrix.sync.aligned.m8n8.x4.shared.b16 {%0,%1,%2,%3}, [%4];"
                 : "=r"(r0), "=r"(r1), "=r"(r2), "=r"(r3) : "r"(addr));
}

// packed f32x2 helpers (base-ISA sm_100+)
__device__ __forceinline__ uint64_t pk2(float lo, float hi) {
    uint64_t r; asm("mov.b64 %0, {%1, %2};" : "=l"(r) : "f"(lo), "f"(hi)); return r;
}
__device__ __forceinline__ void up2(uint64_t v, float& lo, float& hi) {
    asm("mov.b64 {%0, %1}, %2;" : "=f"(lo), "=f"(hi) : "l"(v));
}
__device__ __forceinline__ uint64_t fma2(uint64_t a, uint64_t b, uint64_t c) {
    uint64_t d; asm("fma.rn.f32x2 %0, %1, %2, %3;" : "=l"(d) : "l"(a), "l"(b), "l"(c)); return d;
}
__device__ __forceinline__ uint64_t mul2(uint64_t a, uint64_t b) {
    uint64_t d; asm("mul.rn.f32x2 %0, %1, %2;" : "=l"(d) : "l"(a), "l"(b)); return d;
}
__device__ __forceinline__ float ex2f(float x) {
    float y; asm("ex2.approx.f32 %0, %1;" : "=f"(y) : "f"(x)); return y;
}

// ---------------------------------------------------------------------------
// FP16 mma.sync GEMM (templated BN): C(f32) = A(h)[M,K] @ Wt(h)[N,K]^T + bias
// BM=128, BK=32, 4-stage cp.async ring, ldmatrix fragment loads.
// BNt=128: 8 warps 2x4 (warp 64x32).  BNt=64: 8 warps 4x2 (warp 32x32).
// ---------------------------------------------------------------------------
#define BM 128
#define BK 32
#define NS 4
#define NK (DM / BK)              // 64
#define SAH 40                    // halves per row (80 B, 16B multiple, LDSM conflict-free)
#define A_H (BM * SAH)            // 5120 halves

template <int BNt>
__global__ void __launch_bounds__(256, 2) gemm_h(
    const __half* __restrict__ A,
    const __half* __restrict__ T0, const __half* __restrict__ T1, const __half* __restrict__ T2,
    const float* __restrict__ b0, const float* __restrict__ b1, const float* __restrict__ b2,
    float* __restrict__ C0, float* __restrict__ C1, float* __restrict__ C2)
{
    constexpr int WCN   = BNt / 32;          // warps along n: 4 or 2
    constexpr int MI    = (BNt == 128) ? 4 : 2;   // m-frags per warp
    constexpr int B_H   = BNt * SAH;         // B tile halves
    constexpr int STG_B = (A_H + B_H) * 2;   // stage bytes
    constexpr int BCH   = BNt * 4 / 256;     // B 16B-chunks per thread
    constexpr int SCt   = BNt + 4;           // epilogue f32 stride

    extern __shared__ char smem[];
    uint32_t sbase;
    asm("{ .reg .u64 t; cvta.to.shared.u64 t, %1; cvt.u32.u64 %0, t; }" : "=r"(sbase) : "l"(smem));

    const int z = blockIdx.z;
    const __half* Wt  = (z == 0) ? T0 : (z == 1) ? T1 : T2;
    const float* bias = (z == 0) ? b0 : (z == 1) ? b1 : b2;
    float*       C    = (z == 0) ? C0 : (z == 1) ? C1 : C2;

    const int tid  = threadIdx.x;
    const int lane = tid & 31;
    const int g    = lane >> 2;
    const int t    = lane & 3;
    const int warp = tid >> 5;
    const int mrow0 = (warp / WCN) * (MI * 16);
    const int ncol0 = (warp % WCN) * 32;
    const int bm = blockIdx.y * BM;
    const int bn = blockIdx.x * BNt;

    const uint32_t a_lm = (uint32_t)((mrow0 + (lane & 15)) * SAH + (lane >> 4) * 8);
    const uint32_t b_lm = (uint32_t)((ncol0 + (lane >> 4) * 8 + (lane & 7)) * SAH
                                     + ((lane >> 3) & 1) * 8);

    float acc[MI][4][4];
#pragma unroll
    for (int i = 0; i < MI; i++)
#pragma unroll
        for (int j = 0; j < 4; j++)
#pragma unroll
            for (int e = 0; e < 4; e++) acc[i][j][e] = 0.0f;

    auto fill = [&](int it) {
        const uint32_t ab = sbase + (uint32_t)((it % NS) * STG_B);
        const uint32_t bb = ab + A_H * 2;
        const int kt = it * BK;
        const __half* Ag = A  + (size_t)bm * DM + kt;
        const __half* Bg = Wt + (size_t)bn * DM + kt;
#pragma unroll
        for (int l = 0; l < 2; l++) {
            int i = tid + l * 256;
            int r = i >> 2, c = i & 3;
            cp16(ab + (uint32_t)(r * 80 + c * 16), Ag + (size_t)r * DM + c * 8);
        }
#pragma unroll
        for (int l = 0; l < BCH; l++) {
            int i = tid + l * 256;
            int r = i >> 2, c = i & 3;
            cp16(bb + (uint32_t)(r * 80 + c * 16), Bg + (size_t)r * DM + c * 8);
        }
        asm volatile("cp.async.commit_group;" ::: "memory");
    };

    fill(0); fill(1); fill(2);

#pragma unroll 1
    for (int it = 0; it < NK; it++) {
        asm volatile("cp.async.wait_group 2;" ::: "memory");
        __syncthreads();
        if (it + 3 < NK) fill(it + 3);
        else asm volatile("cp.async.commit_group;" ::: "memory");

        const uint32_t abase = sbase + (uint32_t)((it % NS) * STG_B);
        const uint32_t bbase = abase + A_H * 2;

#pragma unroll
        for (int kk = 0; kk < BK; kk += 16) {
            uint32_t af[MI][4], bf[4][2];
#pragma unroll
            for (int mi = 0; mi < MI; mi++)
                ldsm4(af[mi][0], af[mi][1], af[mi][2], af[mi][3],
                      abase + (a_lm + (uint32_t)(mi * 16 * SAH + kk)) * 2);
#pragma unroll
            for (int p = 0; p < 2; p++)
                ldsm4(bf[2*p][0], bf[2*p][1], bf[2*p+1][0], bf[2*p+1][1],
                      bbase + (b_lm + (uint32_t)(p * 16 * SAH + kk)) * 2);
#pragma unroll
            for (int mi = 0; mi < MI; mi++)
#pragma unroll
                for (int nj = 0; nj < 4; nj++)
                    mma_f16(acc[mi][nj], af[mi], bf[nj]);
        }
    }

    // ---- epilogue: stage accumulators to smem, fused bias, coalesced stores ----
    __syncthreads();
    float* Cs = reinterpret_cast<float*>(smem);
#pragma unroll
    for (int mi = 0; mi < MI; mi++) {
        const int r0 = mrow0 + mi * 16 + g;
#pragma unroll
        for (int nj = 0; nj < 4; nj++) {
            const int c = ncol0 + nj * 8 + 2 * t;
            *reinterpret_cast<float2*>(&Cs[(r0)     * SCt + c]) = make_float2(acc[mi][nj][0], acc[mi][nj][1]);
            *reinterpret_cast<float2*>(&Cs[(r0 + 8) * SCt + c]) = make_float2(acc[mi][nj][2], acc[mi][nj][3]);
        }
    }
    __syncthreads();

#pragma unroll
    for (int l = 0; l < BM * BNt / 4 / 256; l++) {
        int i = tid + l * 256;
        int r = i / (BNt / 4), c = (i % (BNt / 4)) * 4;
        float4 v  = *reinterpret_cast<float4*>(&Cs[r * SCt + c]);
        float4 bb = *reinterpret_cast<const float4*>(&bias[bn + c]);
        v.x += bb.x; v.y += bb.y; v.z += bb.z; v.w += bb.w;
        *reinterpret_cast<float4*>(&C[(size_t)(bm + r) * DM + bn + c]) = v;
    }
}

// ---------------------------------------------------------------------------
// Prep: x -> half;  W[k][n] f32 -> Wt[n][k] half (transpose + convert)
// ---------------------------------------------------------------------------
__global__ void xcvt_kernel(const float* __restrict__ src, __half* __restrict__ dst, int n4)
{
    int i = blockIdx.x * blockDim.x + threadIdx.x;
    if (i < n4) {
        float4 v = reinterpret_cast<const float4*>(src)[i];
        __half2* d = reinterpret_cast<__half2*>(dst) + 2 * i;
        d[0] = __floats2half2_rn(v.x, v.y);
        d[1] = __floats2half2_rn(v.z, v.w);
    }
}

__global__ void wtrans_kernel(
    const float* __restrict__ W0, const float* __restrict__ W1,
    const float* __restrict__ W2, const float* __restrict__ W3)
{
    __shared__ float tsm[32][33];
    const int zz = blockIdx.z;
    const float* src = (zz == 0) ? W0 : (zz == 1) ? W1 : (zz == 2) ? W2 : W3;
    __half* dst = g_wth + (size_t)zz * DM * DM;

    const int n0 = blockIdx.x * 32;
    const int k0 = blockIdx.y * 32;
    const int tid = threadIdx.x;
    const int tx = tid & 31, ty = tid >> 5;

#pragma unroll
    for (int j = ty; j < 32; j += 8)
        tsm[j][tx] = src[(size_t)(k0 + j) * DM + n0 + tx];
    __syncthreads();

#pragma unroll
    for (int idx = tid; idx < 32 * 16; idx += 256) {
        int r = idx >> 4, c = idx & 15;
        __half2 h = __floats2half2_rn(tsm[2 * c][r], tsm[2 * c + 1][r]);
        *reinterpret_cast<__half2*>(&dst[(size_t)(n0 + r) * DM + k0 + 2 * c]) = h;
    }
}

// ---------------------------------------------------------------------------
// Per-token head-mixing attention: 512 threads, split-g (2 halves of 128),
// f32x2 math + ex2 (log2e/sqrt(8) folded into q), smem pair-reduction.
// ---------------------------------------------------------------------------
__global__ void __launch_bounds__(512) attn_kernel()
{
    const int tk   = blockIdx.x;
    const int h    = threadIdx.x & 255;
    const int half = threadIdx.x >> 8;

    __shared__ uint64_t sk[NHEADS * 4];
    __shared__ uint64_t sv[NHEADS * 4];
    __shared__ float red[NHEADS * 9];      // stride 9: gcd(9,32)=1 -> conflict-free

    const uint64_t* qp = reinterpret_cast<const uint64_t*>(&g_q[(size_t)tk * DM]);
    const uint64_t* kp = reinterpret_cast<const uint64_t*>(&g_k[(size_t)tk * DM]);
    const uint64_t* vp = reinterpret_cast<const uint64_t*>(&g_v[(size_t)tk * DM]);

    const float scale = 0.35355339059327373f * 1.4426950408889634f;  // log2e/sqrt(8)
    const uint64_t scl = pk2(scale, scale);

#pragma unroll
    for (int j = threadIdx.x; j < NHEADS * 4; j += 512) {
        sk[j] = kp[j];
        sv[j] = vp[j];
    }
    uint64_t q[4];
#pragma unroll
    for (int j = 0; j < 4; j++)
        q[j] = mul2(qp[h * 4 + j], scl);
    __syncthreads();

    float ls = 0.0f;
    uint64_t a[4] = {0ull, 0ull, 0ull, 0ull};
    const int g0 = half * 128;

#pragma unroll 4
    for (int gi = 0; gi < 128; gi++) {
        const int gg = g0 + gi;
        uint64_t pr = mul2(q[0], sk[gg * 4 + 0]);
        pr = fma2(q[1], sk[gg * 4 + 1], pr);
        pr = fma2(q[2], sk[gg * 4 + 2], pr);
        pr = fma2(q[3], sk[gg * 4 + 3], pr);
        float lo, hi; up2(pr, lo, hi);
        float e = ex2f(lo + hi);
        ls += e;
        uint64_t pe = pk2(e, e);
        a[0] = fma2(pe, sv[gg * 4 + 0], a[0]);
        a[1] = fma2(pe, sv[gg * 4 + 1], a[1]);
        a[2] = fma2(pe, sv[gg * 4 + 2], a[2]);
        a[3] = fma2(pe, sv[gg * 4 + 3], a[3]);
    }

    if (half) {
        float* r = &red[h * 9];
        r[0] = ls;
#pragma unroll
        for (int j = 0; j < 4; j++) {
            float lo, hi; up2(a[j], lo, hi);
            r[1 + 2 * j] = lo;
            r[2 + 2 * j] = hi;
        }
    }
    __syncthreads();
    if (!half) {
        const float* r = &red[h * 9];
        const float inv = 1.0f / (ls + r[0]);
        __half2* o = reinterpret_cast<__half2*>(&g_ah[(size_t)tk * DM + h * 8]);
#pragma unroll
        for (int j = 0; j < 4; j++) {
            float lo, hi; up2(a[j], lo, hi);
            o[j] = __floats2half2_rn((lo + r[1 + 2 * j]) * inv,
                                     (hi + r[2 + 2 * j]) * inv);
        }
    }
}

// ---------------------------------------------------------------------------
// Launch
// ---------------------------------------------------------------------------
extern "C" void kernel_launch(void* const* d_in, const int* in_sizes, int n_in,
                              void* d_out, int out_size)
{
    const float* x  = (const float*)d_in[0];
    // d_in[1] = phase_shift: cos^2+sin^2 cancels analytically; unused.
    const float* Wq = (const float*)d_in[2];
    const float* bq = (const float*)d_in[3];
    const float* Wk = (const float*)d_in[4];
    const float* bk = (const float*)d_in[5];
    const float* Wv = (const float*)d_in[6];
    const float* bv = (const float*)d_in[7];
    const float* Wo = (const float*)d_in[8];
    const float* bo = (const float*)d_in[9];
    float* out = (float*)d_out;

    float *q_p, *k_p, *v_p;
    __half *ah_p, *xh_p, *wt_p;
    cudaGetSymbolAddress((void**)&q_p,  g_q);
    cudaGetSymbolAddress((void**)&k_p,  g_k);
    cudaGetSymbolAddress((void**)&v_p,  g_v);
    cudaGetSymbolAddress((void**)&ah_p, g_ah);
    cudaGetSymbolAddress((void**)&xh_p, g_xh);
    cudaGetSymbolAddress((void**)&wt_p, g_wth);

    constexpr int SM128 = NS * (A_H + 128 * SAH) * 2;   // 81920
    constexpr int SM64  = NS * (A_H + 64  * SAH) * 2;   // 61440
    cudaFuncSetAttribute(gemm_h<128>, cudaFuncAttributeMaxDynamicSharedMemorySize, SM128);
    cudaFuncSetAttribute(gemm_h<64>,  cudaFuncAttributeMaxDynamicSharedMemorySize, SM64);

    const size_t WSZ = (size_t)DM * DM;
    const int nx4 = TOKENS * DM / 4;
    xcvt_kernel<<<(nx4 + 255) / 256, 256>>>(x, xh_p, nx4);
    wtrans_kernel<<<dim3(DM / 32, DM / 32, 4), 256>>>(Wq, Wk, Wv, Wo);

    dim3 gQKV(DM / 128, TOKENS / BM, 3);   // (16, 8, 3)
    gemm_h<128><<<gQKV, 256, SM128>>>(xh_p,
        wt_p, wt_p + WSZ, wt_p + 2 * WSZ,
        bq, bk, bv, q_p, k_p, v_p);

    attn_kernel<<<TOKENS, 512>>>();

    dim3 gO(DM / 64, TOKENS / BM, 1);      // (32, 8, 1) = 256 CTAs
    gemm_h<64><<<gO, 256, SM64>>>(ah_p,
        wt_p + 3 * WSZ, wt_p + 3 * WSZ, wt_p + 3 * WSZ,
        bo, bo, bo, out, out, out);
}